// round 7
// baseline (speedup 1.0000x reference)
#include <cuda_runtime.h>
#include <cstdint>

// Problem constants (fixed shapes per reference)
#define BB 4
#define CC 64
#define NN (512 * 512)
#define KK 400
#define BKK (BB * KK)

// Window-sort accumulate config
#define WIN 4096                 // pixels per CTA window
#define NWIN (NN / WIN)          // 64 windows per batch
#define RCH 4                    // channels per round (float4-grouped)
#define NROUND (CC / RCH)        // 16 rounds
#define SEGLEN 8                 // sorted positions per segment
#define NSEG (WIN / SEGLEN)      // 512 segments (one per thread)
#define ACC_THREADS 512

// Gather config: split channels across 2 CTAs -> 50KB table, 3 CTAs/SM
#define GCH 32
#define GC4 (GCH / 4)            // 8 float4 channel-groups per CTA

// Scratch (no allocations allowed -> __device__ globals)
__device__ float g_sums[BKK * CC];          // [b*K+k][c], L2-resident
__device__ float g_cnt[BKK];                // per-(b,k) pixel counts
__device__ float g_means4[BB * CC * KK];    // [b][c/4][k][c%4] float4-grouped

// ---------------------------------------------------------------------------
// fire-and-forget L2 reductions
// ---------------------------------------------------------------------------
__device__ __forceinline__ void red_add_f32(float* p, float a) {
    asm volatile("red.global.add.f32 [%0], %1;" :: "l"(p), "f"(a) : "memory");
}
__device__ __forceinline__ void red_add_v4(float* p, float4 v) {
    asm volatile("red.global.add.v4.f32 [%0], {%1, %2, %3, %4};"
                 :: "l"(p), "f"(v.x), "f"(v.y), "f"(v.z), "f"(v.w) : "memory");
}

// ---------------------------------------------------------------------------
// Kernel 1: zero the accumulators
// ---------------------------------------------------------------------------
__global__ void zero_kernel() {
    int i = blockIdx.x * blockDim.x + threadIdx.x;
    if (i < BKK * CC) g_sums[i] = 0.0f;
    if (i < BKK)      g_cnt[i]  = 0.0f;
}

// ---------------------------------------------------------------------------
// Kernel 2: window-sorted accumulate, software-pipelined.
//   sort:   hist -> warp-shuffle scan (2 syncs) -> scatter (cell<<12 | pix)
//   rounds: STS staged regs (pixel-major float4 = 4 channels) ->
//           prefetch next round's LDG.128 into regs -> sync ->
//           combine: per-segment run-merge, one LDS.128 + red.v4 per event.
// ---------------------------------------------------------------------------
__global__ __launch_bounds__(ACC_THREADS, 1)
void accum_kernel(const float* __restrict__ f, const int* __restrict__ idx) {
    extern __shared__ char smraw[];
    float4*   f_sm4  = (float4*)smraw;                    // WIN float4 = 64KB
    uint32_t* packed = (uint32_t*)(f_sm4 + WIN);          // WIN = 16KB
    int*      hist   = (int*)(packed + WIN);              // 512
    int*      w      = hist + 512;                        // 512 scatter cursors
    int*      wsum   = w + 512;                           // 32 warp partials

    const int b    = blockIdx.y;
    const int win  = blockIdx.x;
    const int tid  = threadIdx.x;
    const int lane = tid & 31;
    const int wid  = tid >> 5;

    hist[tid] = 0;
    __syncthreads();

    // this thread's 8 pixel indices (2 x int4, coalesced)
    const int4* idxw = reinterpret_cast<const int4*>(idx + (size_t)b * NN + (size_t)win * WIN);
    const int4 ia = idxw[tid];
    const int4 ib = idxw[tid + ACC_THREADS];

    atomicAdd(&hist[ia.x], 1); atomicAdd(&hist[ia.y], 1);
    atomicAdd(&hist[ia.z], 1); atomicAdd(&hist[ia.w], 1);
    atomicAdd(&hist[ib.x], 1); atomicAdd(&hist[ib.y], 1);
    atomicAdd(&hist[ib.z], 1); atomicAdd(&hist[ib.w], 1);
    __syncthreads();

    // counts into g_cnt (exact: small ints in fp32)
    const int h = hist[tid];
    if (tid < KK && h > 0)
        red_add_f32(&g_cnt[b * KK + tid], (float)h);

    // warp-shuffle scan over 512 bins (2 syncs total)
    int v = h;
#pragma unroll
    for (int d = 1; d < 32; d <<= 1) {
        int n = __shfl_up_sync(0xffffffffu, v, d);
        if (lane >= d) v += n;
    }
    if (lane == 31) wsum[wid] = v;
    __syncthreads();
    if (wid == 0 && lane < 16) {
        int s = wsum[lane];
#pragma unroll
        for (int d = 1; d < 16; d <<= 1) {
            int n = __shfl_up_sync(0x0000ffffu, s, d);
            if (lane >= d) s += n;
        }
        wsum[lane] = s;
    }
    __syncthreads();
    w[tid] = (wid ? wsum[wid - 1] : 0) + v - h;   // exclusive prefix
    __syncthreads();

    // scatter sorted order, slot-major: packed[(p%8)*NSEG + p/8]
    {
        const int lp0 = 4 * tid;
        const int lp1 = 4 * (tid + ACC_THREADS);
        int p;
        p = atomicAdd(&w[ia.x], 1); packed[(p & 7) * NSEG + (p >> 3)] = ((uint32_t)ia.x << 12) | (lp0 + 0);
        p = atomicAdd(&w[ia.y], 1); packed[(p & 7) * NSEG + (p >> 3)] = ((uint32_t)ia.y << 12) | (lp0 + 1);
        p = atomicAdd(&w[ia.z], 1); packed[(p & 7) * NSEG + (p >> 3)] = ((uint32_t)ia.z << 12) | (lp0 + 2);
        p = atomicAdd(&w[ia.w], 1); packed[(p & 7) * NSEG + (p >> 3)] = ((uint32_t)ia.w << 12) | (lp0 + 3);
        p = atomicAdd(&w[ib.x], 1); packed[(p & 7) * NSEG + (p >> 3)] = ((uint32_t)ib.x << 12) | (lp1 + 0);
        p = atomicAdd(&w[ib.y], 1); packed[(p & 7) * NSEG + (p >> 3)] = ((uint32_t)ib.y << 12) | (lp1 + 1);
        p = atomicAdd(&w[ib.z], 1); packed[(p & 7) * NSEG + (p >> 3)] = ((uint32_t)ib.z << 12) | (lp1 + 2);
        p = atomicAdd(&w[ib.w], 1); packed[(p & 7) * NSEG + (p >> 3)] = ((uint32_t)ib.w << 12) | (lp1 + 3);
    }

    // --- channel rounds, software pipelined ---
    const float* fwin = f + (size_t)b * CC * NN + (size_t)win * WIN;
    float* srow = g_sums + (size_t)b * KK * CC;
    const int t2 = tid + ACC_THREADS;

    float4 cur[8];   // [0..3]: channels j, pixel quad 4*tid; [4..7]: quad 4*t2
#pragma unroll
    for (int j = 0; j < RCH; j++) {
        const float4* src = reinterpret_cast<const float4*>(fwin + (size_t)j * NN);
        cur[j]     = src[tid];
        cur[4 + j] = src[t2];
    }
    __syncthreads();   // scatter complete before combine reads packed

    for (int r = 0; r < NROUND; r++) {
        // store staged regs, pixel-major (register transpose, STS.128 x8)
        {
            float4 a0 = cur[0], a1 = cur[1], a2 = cur[2], a3 = cur[3];
            f_sm4[4 * tid + 0] = make_float4(a0.x, a1.x, a2.x, a3.x);
            f_sm4[4 * tid + 1] = make_float4(a0.y, a1.y, a2.y, a3.y);
            f_sm4[4 * tid + 2] = make_float4(a0.z, a1.z, a2.z, a3.z);
            f_sm4[4 * tid + 3] = make_float4(a0.w, a1.w, a2.w, a3.w);
            float4 b0 = cur[4], b1 = cur[5], b2 = cur[6], b3 = cur[7];
            f_sm4[4 * t2 + 0] = make_float4(b0.x, b1.x, b2.x, b3.x);
            f_sm4[4 * t2 + 1] = make_float4(b0.y, b1.y, b2.y, b3.y);
            f_sm4[4 * t2 + 2] = make_float4(b0.z, b1.z, b2.z, b3.z);
            f_sm4[4 * t2 + 3] = make_float4(b0.w, b1.w, b2.w, b3.w);
        }
        // prefetch next round while this round's combine runs
        if (r + 1 < NROUND) {
#pragma unroll
            for (int j = 0; j < RCH; j++) {
                const float4* src =
                    reinterpret_cast<const float4*>(fwin + (size_t)((r + 1) * RCH + j) * NN);
                cur[j]     = src[tid];
                cur[4 + j] = src[t2];
            }
        }
        __syncthreads();   // staging visible

        // combine this thread's 8 sorted positions for 4 channels at once
        const int c0 = r * RCH;
        uint32_t pk = packed[tid];
        int    cell = pk >> 12;
        float4 acc  = f_sm4[pk & 4095];
#pragma unroll
        for (int i = 1; i < SEGLEN; i++) {
            pk = packed[i * NSEG + tid];
            const float4 q = f_sm4[pk & 4095];
            const int cl = pk >> 12;
            if (cl != cell) {
                red_add_v4(srow + (size_t)cell * CC + c0, acc);
                cell = cl;
                acc = q;
            } else {
                acc.x += q.x; acc.y += q.y; acc.z += q.z; acc.w += q.w;
            }
        }
        red_add_v4(srow + (size_t)cell * CC + c0, acc);
        __syncthreads();   // combine done before next STS overwrites f_sm4
    }
}

// ---------------------------------------------------------------------------
// Kernel 3: means = sums / max(cnt,1), float4-channel-grouped:
// g_means4[b][c/4][k][c%4]
// ---------------------------------------------------------------------------
__global__ void finalize_kernel() {
    int i = blockIdx.x * blockDim.x + threadIdx.x;
    if (i >= BKK * CC) return;
    const int bk = i / CC;
    const int c  = i % CC;
    const float cnt = fmaxf(g_cnt[bk], 1.0f);
    const float m = g_sums[i] / cnt;
    const int b = bk / KK;
    const int k = bk % KK;
    g_means4[((((size_t)b * (CC / 4) + (c >> 2)) * KK) + k) * 4 + (c & 3)] = m;
}

// ---------------------------------------------------------------------------
// Kernel 4: gather, channel-split (32 ch per CTA -> 50KB table, 3 CTAs/SM).
// One LDS.128 per (4-channel group, pixel); register transpose -> STG.128.
// ---------------------------------------------------------------------------
__global__ __launch_bounds__(512, 3)
void gather_kernel(const int* __restrict__ idx, float* __restrict__ out) {
    extern __shared__ float4 sm4[];   // GC4*KK float4 = 51200 B
    const int b = blockIdx.y;
    const int z = blockIdx.z;

    const float4* tb = reinterpret_cast<const float4*>(g_means4)
                     + ((size_t)b * (CC / 4) + (size_t)z * GC4) * KK;
    for (int i = threadIdx.x; i < GC4 * KK; i += blockDim.x)
        sm4[i] = tb[i];
    __syncthreads();

    const int n4 = NN / 4;
    const int4* idx4 = reinterpret_cast<const int4*>(idx + (size_t)b * NN);
    float* outb = out + (size_t)b * CC * NN + (size_t)z * GCH * NN;

    for (int t = blockIdx.x * blockDim.x + threadIdx.x; t < n4;
         t += gridDim.x * blockDim.x) {
        const int4 id = idx4[t];
#pragma unroll
        for (int c4 = 0; c4 < GC4; c4++) {
            const float4 q0 = sm4[c4 * KK + id.x];
            const float4 q1 = sm4[c4 * KK + id.y];
            const float4 q2 = sm4[c4 * KK + id.z];
            const float4 q3 = sm4[c4 * KK + id.w];
            float4* o0 = reinterpret_cast<float4*>(outb + (size_t)(4 * c4 + 0) * NN);
            float4* o1 = reinterpret_cast<float4*>(outb + (size_t)(4 * c4 + 1) * NN);
            float4* o2 = reinterpret_cast<float4*>(outb + (size_t)(4 * c4 + 2) * NN);
            float4* o3 = reinterpret_cast<float4*>(outb + (size_t)(4 * c4 + 3) * NN);
            o0[t] = make_float4(q0.x, q1.x, q2.x, q3.x);
            o1[t] = make_float4(q0.y, q1.y, q2.y, q3.y);
            o2[t] = make_float4(q0.z, q1.z, q2.z, q3.z);
            o3[t] = make_float4(q0.w, q1.w, q2.w, q3.w);
        }
    }
}

// ---------------------------------------------------------------------------
// Launch: zero -> pipelined window-sort accumulate -> finalize -> gather
// ---------------------------------------------------------------------------
extern "C" void kernel_launch(void* const* d_in, const int* in_sizes, int n_in,
                              void* d_out, int out_size) {
    const float* features = (const float*)d_in[0];   // [B, C, N] fp32
    const int*   spixel   = (const int*)d_in[1];     // [B, N] int32
    float*       out      = (float*)d_out;           // [B, C, N] fp32

    (void)in_sizes; (void)n_in; (void)out_size;

    const int accum_smem = WIN * 16 + WIN * 4 + (512 + 512 + 32) * 4;  // 86144 B
    const int gather_smem = GC4 * KK * (int)sizeof(float4);            // 51200 B
    cudaFuncSetAttribute(accum_kernel,
                         cudaFuncAttributeMaxDynamicSharedMemorySize, accum_smem);
    cudaFuncSetAttribute(gather_kernel,
                         cudaFuncAttributeMaxDynamicSharedMemorySize, gather_smem);

    {   // zero accumulators
        int n = BKK * CC;
        zero_kernel<<<(n + 255) / 256, 256>>>();
    }
    {   // window-sorted scatter-reduce: 64 windows x 4 batches = 256 CTAs
        dim3 grid(NWIN, BB);
        accum_kernel<<<grid, ACC_THREADS, accum_smem>>>(features, spixel);
    }
    {   // means (+ channel-group transpose)
        int n = BKK * CC;
        finalize_kernel<<<(n + 255) / 256, 256>>>();
    }
    {   // gather: 56 x 4 batches x 2 channel-halves = 448 CTAs (3/SM)
        dim3 grid(56, BB, 2);
        gather_kernel<<<grid, 512, gather_smem>>>(spixel, out);
    }
}

// round 9
// speedup vs baseline: 1.0231x; 1.0231x over previous
#include <cuda_runtime.h>
#include <cstdint>

// Problem constants (fixed shapes per reference)
#define BB 4
#define CC 64
#define NN (512 * 512)
#define KK 400
#define BKK (BB * KK)

// Window-sort accumulate config
#define WIN 4096                 // pixels per CTA window
#define NWIN (NN / WIN)          // 64 windows per batch
#define RCH 4                    // channels per round (float4-grouped)
#define NROUND (CC / RCH)        // 16 rounds
#define SEGLEN 8                 // sorted positions per segment
#define NSEG (WIN / SEGLEN)      // 512 segments (one per thread)
#define ACC_THREADS 512

// Scratch (no allocations allowed -> __device__ globals)
__device__ float g_sums[BKK * CC];          // [b*K+k][c], L2-resident
__device__ float g_cnt[BKK];                // per-(b,k) pixel counts
__device__ float g_means4[BB * CC * KK];    // [b][c/4][k][c%4] float4-grouped

// ---------------------------------------------------------------------------
// fire-and-forget L2 reductions (plain + predicated-in-asm: no BSSY/BSYNC)
// ---------------------------------------------------------------------------
__device__ __forceinline__ void red_add_f32(float* p, float a) {
    asm volatile("red.global.add.f32 [%0], %1;" :: "l"(p), "f"(a) : "memory");
}
__device__ __forceinline__ void red_add_v4(float* p, float4 v) {
    asm volatile("red.global.add.v4.f32 [%0], {%1, %2, %3, %4};"
                 :: "l"(p), "f"(v.x), "f"(v.y), "f"(v.z), "f"(v.w) : "memory");
}
__device__ __forceinline__ void red_add_v4_pred(float* p, float4 v, int pred) {
    asm volatile("{\n\t"
                 ".reg .pred q;\n\t"
                 "setp.ne.s32 q, %5, 0;\n\t"
                 "@q red.global.add.v4.f32 [%0], {%1, %2, %3, %4};\n\t"
                 "}"
                 :: "l"(p), "f"(v.x), "f"(v.y), "f"(v.z), "f"(v.w), "r"(pred)
                 : "memory");
}

// ---------------------------------------------------------------------------
// Kernel 1: zero the accumulators
// ---------------------------------------------------------------------------
__global__ void zero_kernel() {
    int i = blockIdx.x * blockDim.x + threadIdx.x;
    if (i < BKK * CC) g_sums[i] = 0.0f;
    if (i < BKK)      g_cnt[i]  = 0.0f;
}

// ---------------------------------------------------------------------------
// Kernel 2: window-sorted accumulate.
//   sort:   hist -> warp-shuffle scan -> scatter (cell<<12 | localpix)
//   rounds: stage 4 channels pixel-major (float4) in smem, per-segment
//           run-merge with PREDICATED red.v4 (no divergent branches).
// ---------------------------------------------------------------------------
__global__ __launch_bounds__(ACC_THREADS, 1)
void accum_kernel(const float* __restrict__ f, const int* __restrict__ idx) {
    extern __shared__ char smraw[];
    float4*   f_sm4  = (float4*)smraw;                    // WIN float4 = 64KB
    uint32_t* packed = (uint32_t*)(f_sm4 + WIN);          // WIN = 16KB
    int*      hist   = (int*)(packed + WIN);              // 512
    int*      w      = hist + 512;                        // 512 scatter cursors
    int*      wsum   = w + 512;                           // 32 warp partials

    const int b    = blockIdx.y;
    const int win  = blockIdx.x;
    const int tid  = threadIdx.x;
    const int lane = tid & 31;
    const int wid  = tid >> 5;

    hist[tid] = 0;
    __syncthreads();

    // this thread's 8 pixel indices (2 x int4, coalesced, streaming)
    const int4* idxw = reinterpret_cast<const int4*>(idx + (size_t)b * NN + (size_t)win * WIN);
    const int4 ia = __ldcs(&idxw[tid]);
    const int4 ib = __ldcs(&idxw[tid + ACC_THREADS]);

    atomicAdd(&hist[ia.x], 1); atomicAdd(&hist[ia.y], 1);
    atomicAdd(&hist[ia.z], 1); atomicAdd(&hist[ia.w], 1);
    atomicAdd(&hist[ib.x], 1); atomicAdd(&hist[ib.y], 1);
    atomicAdd(&hist[ib.z], 1); atomicAdd(&hist[ib.w], 1);
    __syncthreads();

    // counts into g_cnt (exact: small ints in fp32)
    const int h = hist[tid];
    if (tid < KK && h > 0)
        red_add_f32(&g_cnt[b * KK + tid], (float)h);

    // warp-shuffle scan over 512 bins
    int v = h;
#pragma unroll
    for (int d = 1; d < 32; d <<= 1) {
        int n = __shfl_up_sync(0xffffffffu, v, d);
        if (lane >= d) v += n;
    }
    if (lane == 31) wsum[wid] = v;
    __syncthreads();
    if (wid == 0 && lane < 16) {
        int s = wsum[lane];
#pragma unroll
        for (int d = 1; d < 16; d <<= 1) {
            int n = __shfl_up_sync(0x0000ffffu, s, d);
            if (lane >= d) s += n;
        }
        wsum[lane] = s;
    }
    __syncthreads();
    w[tid] = (wid ? wsum[wid - 1] : 0) + v - h;   // exclusive prefix
    __syncthreads();

    // scatter sorted order, slot-major: packed[(p%8)*NSEG + p/8]
    {
        const int lp0 = 4 * tid;
        const int lp1 = 4 * (tid + ACC_THREADS);
        int p;
        p = atomicAdd(&w[ia.x], 1); packed[(p & 7) * NSEG + (p >> 3)] = ((uint32_t)ia.x << 12) | (lp0 + 0);
        p = atomicAdd(&w[ia.y], 1); packed[(p & 7) * NSEG + (p >> 3)] = ((uint32_t)ia.y << 12) | (lp0 + 1);
        p = atomicAdd(&w[ia.z], 1); packed[(p & 7) * NSEG + (p >> 3)] = ((uint32_t)ia.z << 12) | (lp0 + 2);
        p = atomicAdd(&w[ia.w], 1); packed[(p & 7) * NSEG + (p >> 3)] = ((uint32_t)ia.w << 12) | (lp0 + 3);
        p = atomicAdd(&w[ib.x], 1); packed[(p & 7) * NSEG + (p >> 3)] = ((uint32_t)ib.x << 12) | (lp1 + 0);
        p = atomicAdd(&w[ib.y], 1); packed[(p & 7) * NSEG + (p >> 3)] = ((uint32_t)ib.y << 12) | (lp1 + 1);
        p = atomicAdd(&w[ib.z], 1); packed[(p & 7) * NSEG + (p >> 3)] = ((uint32_t)ib.z << 12) | (lp1 + 2);
        p = atomicAdd(&w[ib.w], 1); packed[(p & 7) * NSEG + (p >> 3)] = ((uint32_t)ib.w << 12) | (lp1 + 3);
    }

    // --- channel rounds (prefetch next round's LDG into regs, streaming) ---
    const float* fwin = f + (size_t)b * CC * NN + (size_t)win * WIN;
    float* srow = g_sums + (size_t)b * KK * CC;
    const int t2 = tid + ACC_THREADS;

    float4 cur[8];
#pragma unroll
    for (int j = 0; j < RCH; j++) {
        const float4* src = reinterpret_cast<const float4*>(fwin + (size_t)j * NN);
        cur[j]     = __ldcs(&src[tid]);
        cur[4 + j] = __ldcs(&src[t2]);
    }
    __syncthreads();   // scatter complete before combine reads packed

    for (int r = 0; r < NROUND; r++) {
        // store staged regs, pixel-major (register transpose, STS.128 x8)
        {
            float4 a0 = cur[0], a1 = cur[1], a2 = cur[2], a3 = cur[3];
            f_sm4[4 * tid + 0] = make_float4(a0.x, a1.x, a2.x, a3.x);
            f_sm4[4 * tid + 1] = make_float4(a0.y, a1.y, a2.y, a3.y);
            f_sm4[4 * tid + 2] = make_float4(a0.z, a1.z, a2.z, a3.z);
            f_sm4[4 * tid + 3] = make_float4(a0.w, a1.w, a2.w, a3.w);
            float4 b0 = cur[4], b1 = cur[5], b2 = cur[6], b3 = cur[7];
            f_sm4[4 * t2 + 0] = make_float4(b0.x, b1.x, b2.x, b3.x);
            f_sm4[4 * t2 + 1] = make_float4(b0.y, b1.y, b2.y, b3.y);
            f_sm4[4 * t2 + 2] = make_float4(b0.z, b1.z, b2.z, b3.z);
            f_sm4[4 * t2 + 3] = make_float4(b0.w, b1.w, b2.w, b3.w);
        }
        if (r + 1 < NROUND) {
#pragma unroll
            for (int j = 0; j < RCH; j++) {
                const float4* src =
                    reinterpret_cast<const float4*>(fwin + (size_t)((r + 1) * RCH + j) * NN);
                cur[j]     = __ldcs(&src[tid]);
                cur[4 + j] = __ldcs(&src[t2]);
            }
        }
        __syncthreads();   // staging visible

        // branch-free combine of this thread's 8 sorted positions (4 chans)
        const int c0 = r * RCH;
        uint32_t pk = packed[tid];
        int    cell = pk >> 12;
        float4 acc  = f_sm4[pk & 4095];
#pragma unroll
        for (int i = 1; i < SEGLEN; i++) {
            pk = packed[i * NSEG + tid];
            const float4 q = f_sm4[pk & 4095];
            const int cl = pk >> 12;
            const int nb = (cl != cell) ? 1 : 0;
            red_add_v4_pred(srow + (size_t)cell * CC + c0, acc, nb);
            acc.x = nb ? q.x : acc.x + q.x;
            acc.y = nb ? q.y : acc.y + q.y;
            acc.z = nb ? q.z : acc.z + q.z;
            acc.w = nb ? q.w : acc.w + q.w;
            cell = cl;
        }
        red_add_v4(srow + (size_t)cell * CC + c0, acc);
        __syncthreads();   // combine done before next STS overwrites f_sm4
    }
}

// ---------------------------------------------------------------------------
// Kernel 3: means = sums / max(cnt,1), float4-channel-grouped:
// g_means4[b][c/4][k][c%4]
// ---------------------------------------------------------------------------
__global__ void finalize_kernel() {
    int i = blockIdx.x * blockDim.x + threadIdx.x;
    if (i >= BKK * CC) return;
    const int bk = i / CC;
    const int c  = i % CC;
    const float cnt = fmaxf(g_cnt[bk], 1.0f);
    const float m = g_sums[i] / cnt;
    const int b = bk / KK;
    const int k = bk % KK;
    g_means4[((((size_t)b * (CC / 4) + (c >> 2)) * KK) + k) * 4 + (c & 3)] = m;
}

// ---------------------------------------------------------------------------
// Kernel 4: gather (R5 config: full 64 channels, 100KB table, 2 CTAs/SM).
// One LDS.128 per (4-channel group, pixel); register transpose -> STG.128
// with .cs streaming hint (output never re-read).
// ---------------------------------------------------------------------------
__global__ void gather_kernel(const int* __restrict__ idx, float* __restrict__ out) {
    extern __shared__ float4 sm4[];   // (CC/4)*KK float4 = 102400 B
    const int b = blockIdx.y;

    const float4* tb = reinterpret_cast<const float4*>(g_means4) + (size_t)b * (CC / 4) * KK;
    for (int i = threadIdx.x; i < (CC / 4) * KK; i += blockDim.x)
        sm4[i] = tb[i];
    __syncthreads();

    const int n4 = NN / 4;
    const int4* idx4 = reinterpret_cast<const int4*>(idx + (size_t)b * NN);
    float* outb = out + (size_t)b * CC * NN;

    for (int t = blockIdx.x * blockDim.x + threadIdx.x; t < n4;
         t += gridDim.x * blockDim.x) {
        const int4 id = __ldcs(&idx4[t]);
#pragma unroll
        for (int c4 = 0; c4 < CC / 4; c4++) {
            const float4 q0 = sm4[c4 * KK + id.x];
            const float4 q1 = sm4[c4 * KK + id.y];
            const float4 q2 = sm4[c4 * KK + id.z];
            const float4 q3 = sm4[c4 * KK + id.w];
            float4* o0 = reinterpret_cast<float4*>(outb + (size_t)(4 * c4 + 0) * NN);
            float4* o1 = reinterpret_cast<float4*>(outb + (size_t)(4 * c4 + 1) * NN);
            float4* o2 = reinterpret_cast<float4*>(outb + (size_t)(4 * c4 + 2) * NN);
            float4* o3 = reinterpret_cast<float4*>(outb + (size_t)(4 * c4 + 3) * NN);
            __stcs(&o0[t], make_float4(q0.x, q1.x, q2.x, q3.x));
            __stcs(&o1[t], make_float4(q0.y, q1.y, q2.y, q3.y));
            __stcs(&o2[t], make_float4(q0.z, q1.z, q2.z, q3.z));
            __stcs(&o3[t], make_float4(q0.w, q1.w, q2.w, q3.w));
        }
    }
}

// ---------------------------------------------------------------------------
// Launch: zero -> window-sort accumulate -> finalize -> gather
// ---------------------------------------------------------------------------
extern "C" void kernel_launch(void* const* d_in, const int* in_sizes, int n_in,
                              void* d_out, int out_size) {
    const float* features = (const float*)d_in[0];   // [B, C, N] fp32
    const int*   spixel   = (const int*)d_in[1];     // [B, N] int32
    float*       out      = (float*)d_out;           // [B, C, N] fp32

    (void)in_sizes; (void)n_in; (void)out_size;

    const int accum_smem  = WIN * 16 + WIN * 4 + (512 + 512 + 32) * 4;  // 86144 B
    const int gather_smem = (CC / 4) * KK * (int)sizeof(float4);        // 102400 B
    cudaFuncSetAttribute(accum_kernel,
                         cudaFuncAttributeMaxDynamicSharedMemorySize, accum_smem);
    cudaFuncSetAttribute(gather_kernel,
                         cudaFuncAttributeMaxDynamicSharedMemorySize, gather_smem);

    {   // zero accumulators
        int n = BKK * CC;
        zero_kernel<<<(n + 255) / 256, 256>>>();
    }
    {   // window-sorted scatter-reduce: 64 windows x 4 batches = 256 CTAs
        dim3 grid(NWIN, BB);
        accum_kernel<<<grid, ACC_THREADS, accum_smem>>>(features, spixel);
    }
    {   // means (+ channel-group transpose)
        int n = BKK * CC;
        finalize_kernel<<<(n + 255) / 256, 256>>>();
    }
    {   // gather: 74 x 4 CTAs, 512 threads, 100KB smem (2 CTAs/SM)
        dim3 grid(74, BB);
        gather_kernel<<<grid, 512, gather_smem>>>(spixel, out);
    }
}